// round 10
// baseline (speedup 1.0000x reference)
#include <cuda_runtime.h>
#include <cuda_fp16.h>

#define N_NODES 20000
#define F 256
#define R 32
#define NEI2 (R * R)
#define BN_EPS 1e-5f
#define FULLM 0xffffffffu

// ---------------- scratch (no allocations allowed) ----------------
__device__ float g_K[N_NODES];
__device__ float g_Q[N_NODES];
__device__ __align__(16) float g_QA[(size_t)N_NODES * R];    // Q[adj[c][j]] (NaN if masked)
__device__ __align__(16) unsigned short g_inh[(size_t)N_NODES * F];  // fp16 copy of input
__device__ __align__(16) float g_agg[(size_t)N_NODES * F];   // aggregated rows, tf32-rounded
__device__ __align__(16) float g_Wt[F * F];                  // W, tf32-rounded
__device__ float g_fin[(size_t)N_NODES * F];   // pre-BN final_h
__device__ float g_colsum[F];
__device__ float g_colsumsq[F];

__device__ __forceinline__ float nan_f()  { return __int_as_float(0x7fffffffu); }

__device__ __forceinline__ unsigned f2tf32(float x) {
    unsigned r;
    asm("cvt.rna.tf32.f32 %0, %1;" : "=r"(r) : "f"(x));
    return r;
}
__device__ __forceinline__ float tf32r(float x) { return __uint_as_float(f2tf32(x)); }

// order-preserving float -> uint map (never 0 for non-NaN input)
__device__ __forceinline__ unsigned fmap(float v) {
    unsigned b = __float_as_uint(v);
    return (b & 0x80000000u) ? ~b : (b | 0x80000000u);
}

__device__ __forceinline__ void cp16(unsigned dst, const void* src, int sz) {
    asm volatile("cp.async.cg.shared.global [%0], [%1], 16, %2;"
                 :: "r"(dst), "l"(src), "r"(sz));
}

// ---------------- kernel 1: Key/Query scalars + fp16 copy + BN-acc zeroing ----------------
__global__ void kq_kernel(const float* __restrict__ input,
                          const float* __restrict__ Wk,
                          const float* __restrict__ Wq) {
    if (blockIdx.x == 0) {
        int t = threadIdx.x;
        if (t < F) { g_colsum[t] = 0.0f; g_colsumsq[t] = 0.0f; }
    }
    int warp = (blockIdx.x * blockDim.x + threadIdx.x) >> 5;
    int lane = threadIdx.x & 31;
    if (warp >= N_NODES) return;
    const float4* row = (const float4*)(input + (size_t)warp * F);
    const float4* wk4 = (const float4*)Wk;
    const float4* wq4 = (const float4*)Wq;
    float4 x0 = row[lane];
    float4 x1 = row[32 + lane];
    float sk, sq;
    {
        float4 a = wk4[lane], a1 = wk4[32 + lane];
        sk = x0.x * a.x + x0.y * a.y + x0.z * a.z + x0.w * a.w
           + x1.x * a1.x + x1.y * a1.y + x1.z * a1.z + x1.w * a1.w;
        float4 b = wq4[lane], b1 = wq4[32 + lane];
        sq = x0.x * b.x + x0.y * b.y + x0.z * b.z + x0.w * b.w
           + x1.x * b1.x + x1.y * b1.y + x1.z * b1.z + x1.w * b1.w;
    }
    {
        __half2 h0 = __float22half2_rn(make_float2(x0.x, x0.y));
        __half2 h1 = __float22half2_rn(make_float2(x0.z, x0.w));
        __half2 h2 = __float22half2_rn(make_float2(x1.x, x1.y));
        __half2 h3 = __float22half2_rn(make_float2(x1.z, x1.w));
        uint2 p0 = make_uint2(*(unsigned*)&h0, *(unsigned*)&h1);
        uint2 p1 = make_uint2(*(unsigned*)&h2, *(unsigned*)&h3);
        *(uint2*)(g_inh + (size_t)warp * F + 4 * lane)       = p0;
        *(uint2*)(g_inh + (size_t)warp * F + 128 + 4 * lane) = p1;
    }
#pragma unroll
    for (int o = 16; o; o >>= 1) {
        sk += __shfl_xor_sync(FULLM, sk, o);
        sq += __shfl_xor_sync(FULLM, sq, o);
    }
    if (lane == 0) { g_K[warp] = sk; g_Q[warp] = sq; }
}

// ---------------- kernel 1b: QA table + W tf32 conversion + rf copy ----------------
__global__ void qa_kernel(const int* __restrict__ adj,
                          const float* __restrict__ W,
                          const int* __restrict__ rf,
                          float* __restrict__ out_rf) {
    int idx = blockIdx.x * blockDim.x + threadIdx.x;
    if (idx < F * F) g_Wt[idx] = tf32r(W[idx]);
    if (idx >= N_NODES * R) return;
    int id = adj[idx];
    g_QA[idx] = (id == N_NODES - 1) ? nan_f() : g_Q[id];
    if (out_rf) out_rf[idx] = (float)rf[idx];
}

// ---------------- kernel 2: attention softmax + fp16 aggregation (tf32-rounded out) ----------------
__global__ void agg_kernel(const float* __restrict__ input,
                           const int* __restrict__ rf) {
    int gw = (blockIdx.x * blockDim.x + threadIdx.x) >> 5;
    int lane = threadIdx.x & 31;
    if (gw >= N_NODES) return;

    int rid = rf[gw * R + lane];
    float v = (rid == N_NODES - 1) ? -3.0e38f : g_K[gw] * g_Q[rid];
    float m = v;
#pragma unroll
    for (int o = 16; o; o >>= 1) m = fmaxf(m, __shfl_xor_sync(FULLM, m, o));
    float e = expf(v - m);
    float s = e;
#pragma unroll
    for (int o = 16; o; o >>= 1) s += __shfl_xor_sync(FULLM, s, o);
    float wgt = e / s;

    const float4* own = (const float4*)(input + (size_t)gw * F);
    float4 o0 = own[lane * 2];
    float4 o1 = own[lane * 2 + 1];
    float acc[8] = {o0.x, o0.y, o0.z, o0.w, o1.x, o1.y, o1.z, o1.w};

#pragma unroll 4
    for (int j = 0; j < R; j++) {
        float wj = __shfl_sync(FULLM, wgt, j);
        int id = __shfl_sync(FULLM, rid, j);
        if (wj != 0.0f) {
            uint4 h = *(const uint4*)(g_inh + (size_t)id * F + lane * 8);
            float2 f;
            f = __half22float2(*(__half2*)&h.x); acc[0] += wj * f.x; acc[1] += wj * f.y;
            f = __half22float2(*(__half2*)&h.y); acc[2] += wj * f.x; acc[3] += wj * f.y;
            f = __half22float2(*(__half2*)&h.z); acc[4] += wj * f.x; acc[5] += wj * f.y;
            f = __half22float2(*(__half2*)&h.w); acc[6] += wj * f.x; acc[7] += wj * f.y;
        }
    }
    float4* dst = (float4*)(g_agg + (size_t)gw * F);
    dst[lane * 2]     = make_float4(tf32r(acc[0]), tf32r(acc[1]), tf32r(acc[2]), tf32r(acc[3]));
    dst[lane * 2 + 1] = make_float4(tf32r(acc[4]), tf32r(acc[5]), tf32r(acc[6]), tf32r(acc[7]));
}

// ---------------- fused kernel: expand (ALU-bound) + gemm (tensor/latency-bound) ----------------
// The two roles are independent after agg and stress DISJOINT pipes: gemm blocks idle on
// MMA/smem latency (issue 15%), expand blocks are issue-bound ALU (issue 51%). Co-residency
// lets expand fill gemm's idle issue slots. Bresenham-interleaved role assignment.
#define EWPB 8
#define VSTR 33
#define GBM 128
#define GBN 128
#define GKC 32
#define ASTR 36
#define BSTR 136
#define ASZ (GBM * ASTR)
#define BSZ (GKC * BSTR)
#define STG (ASZ + BSZ)
#define FUSED_SMEM (2 * STG * 4)           // 71680 bytes (expand needs only 33792)
#define NKT (F / GKC)
#define GEMM_BLOCKS (((N_NODES + GBM - 1) / GBM) * (F / GBN))   // 157*2 = 314
#define EXP_BLOCKS (N_NODES / EWPB)                              // 2500
#define TOT_BLOCKS (GEMM_BLOCKS + EXP_BLOCKS)                    // 2814

__device__ __forceinline__ void gemm_body(int gidx, float* sm) {
    unsigned smb = (unsigned)__cvta_generic_to_shared(sm);
    int bm = (gidx % ((N_NODES + GBM - 1) / GBM)) * GBM;
    int bn = (gidx / ((N_NODES + GBM - 1) / GBM)) * GBN;
    int t = threadIdx.x;
    int lane = t & 31, warp = t >> 5;
    int warp_m = warp >> 1, warp_n = warp & 1;
    int g = lane >> 2, tg = lane & 3;
    int m0 = warp_m * 32, n0 = warp_n * 64;

    int arow = t >> 1, akc = (t & 1) * 16;
    int bk = t >> 3, bc = (t & 7) * 16;
    int gr = bm + arow;
    int asz = (gr < N_NODES) ? 16 : 0;
    const float* asrc = g_agg + (size_t)(gr < N_NODES ? gr : 0) * F + akc;
    const float* bsrc = g_Wt + (size_t)bk * F + bn + bc;

    float acc[2][8][4];
#pragma unroll
    for (int mt = 0; mt < 2; mt++)
#pragma unroll
        for (int nt = 0; nt < 8; nt++)
#pragma unroll
            for (int c = 0; c < 4; c++) acc[mt][nt][c] = 0.0f;

    auto issue = [&](int stage, int kt) {
        unsigned ab = smb + (stage * STG + arow * ASTR + akc) * 4;
        const float* as = asrc + kt;
#pragma unroll
        for (int q = 0; q < 4; q++) cp16(ab + q * 16, as + q * 4, asz);
        unsigned bb = smb + (stage * STG + ASZ + bk * BSTR + bc) * 4;
        const float* bs = bsrc + (size_t)kt * F;
#pragma unroll
        for (int q = 0; q < 4; q++) cp16(bb + q * 16, bs + q * 4, 16);
        asm volatile("cp.async.commit_group;");
    };

    issue(0, 0);

    for (int s = 0; s < NKT; s++) {
        if (s + 1 < NKT) {
            issue((s + 1) & 1, (s + 1) * GKC);
            asm volatile("cp.async.wait_group 1;");
        } else {
            asm volatile("cp.async.wait_group 0;");
        }
        __syncthreads();

        const unsigned* As = (const unsigned*)(sm + (s & 1) * STG);
        const unsigned* Bs = (const unsigned*)(sm + (s & 1) * STG + ASZ);
#pragma unroll
        for (int kk = 0; kk < 4; kk++) {
            int k8 = kk * 8;
            unsigned af[2][4];
#pragma unroll
            for (int mt = 0; mt < 2; mt++) {
                int r0 = m0 + mt * 16 + g;
                af[mt][0] = As[r0 * ASTR + k8 + tg];
                af[mt][1] = As[(r0 + 8) * ASTR + k8 + tg];
                af[mt][2] = As[r0 * ASTR + k8 + tg + 4];
                af[mt][3] = As[(r0 + 8) * ASTR + k8 + tg + 4];
            }
            unsigned bf[8][2];
#pragma unroll
            for (int nt = 0; nt < 8; nt++) {
                bf[nt][0] = Bs[(k8 + tg) * BSTR + n0 + nt * 8 + g];
                bf[nt][1] = Bs[(k8 + tg + 4) * BSTR + n0 + nt * 8 + g];
            }
#pragma unroll
            for (int mt = 0; mt < 2; mt++)
#pragma unroll
                for (int nt = 0; nt < 8; nt++) {
                    asm volatile(
                        "mma.sync.aligned.m16n8k8.row.col.f32.tf32.tf32.f32 "
                        "{%0,%1,%2,%3}, {%4,%5,%6,%7}, {%8,%9}, {%0,%1,%2,%3};"
                        : "+f"(acc[mt][nt][0]), "+f"(acc[mt][nt][1]),
                          "+f"(acc[mt][nt][2]), "+f"(acc[mt][nt][3])
                        : "r"(af[mt][0]), "r"(af[mt][1]), "r"(af[mt][2]), "r"(af[mt][3]),
                          "r"(bf[nt][0]), "r"(bf[nt][1]));
                }
        }
        __syncthreads();
    }

    // store C + fused column sum / sum-of-squares (OOB rows are exact zeros)
#pragma unroll
    for (int mt = 0; mt < 2; mt++) {
        int row0 = bm + m0 + mt * 16 + g;
        int row1 = row0 + 8;
#pragma unroll
        for (int nt = 0; nt < 8; nt++) {
            int col = bn + n0 + nt * 8 + 2 * tg;
            if (row0 < N_NODES)
                *(float2*)(g_fin + (size_t)row0 * F + col) =
                    make_float2(acc[mt][nt][0], acc[mt][nt][1]);
            if (row1 < N_NODES)
                *(float2*)(g_fin + (size_t)row1 * F + col) =
                    make_float2(acc[mt][nt][2], acc[mt][nt][3]);
        }
    }
#pragma unroll
    for (int nt = 0; nt < 8; nt++) {
        float s0 = acc[0][nt][0] + acc[0][nt][2] + acc[1][nt][0] + acc[1][nt][2];
        float s1 = acc[0][nt][1] + acc[0][nt][3] + acc[1][nt][1] + acc[1][nt][3];
        float q0 = acc[0][nt][0] * acc[0][nt][0] + acc[0][nt][2] * acc[0][nt][2]
                 + acc[1][nt][0] * acc[1][nt][0] + acc[1][nt][2] * acc[1][nt][2];
        float q1 = acc[0][nt][1] * acc[0][nt][1] + acc[0][nt][3] * acc[0][nt][3]
                 + acc[1][nt][1] * acc[1][nt][1] + acc[1][nt][3] * acc[1][nt][3];
#pragma unroll
        for (int o = 4; o <= 16; o <<= 1) {
            s0 += __shfl_xor_sync(FULLM, s0, o);
            s1 += __shfl_xor_sync(FULLM, s1, o);
            q0 += __shfl_xor_sync(FULLM, q0, o);
            q1 += __shfl_xor_sync(FULLM, q1, o);
        }
        if (lane < 4) {
            int col = bn + n0 + nt * 8 + 2 * tg;
            atomicAdd(&g_colsum[col], s0);
            atomicAdd(&g_colsum[col + 1], s1);
            atomicAdd(&g_colsumsq[col], q0);
            atomicAdd(&g_colsumsq[col + 1], q1);
        }
    }
}

__device__ __forceinline__ void expand_body(int eidx,
                                            const int* __restrict__ rf,
                                            const int* __restrict__ adj,
                                            float* __restrict__ out_expand,
                                            unsigned* Vb) {
    int w = threadIdx.x >> 5;
    int lane = threadIdx.x & 31;
    int i = eidx * EWPB + w;
    unsigned* V = Vb + w * (R * VSTR);

    float key = g_K[i];
    int rfl = rf[i * R + lane];

    // load own QA row (8 x float4); per-lane top-1 (smallest j among equals)
    unsigned b0v = 0;
    int b0j = 0;
    const float4* qrow = (const float4*)(g_QA + (size_t)rfl * R);
    unsigned* Vrow = &V[lane * VSTR];
#pragma unroll
    for (int q = 0; q < 8; q++) {
        float4 x = qrow[q];
        float v0 = (x.x != x.x) ? -3.0e38f : key * x.x;
        float v1 = (x.y != x.y) ? -3.0e38f : key * x.y;
        float v2 = (x.z != x.z) ? -3.0e38f : key * x.z;
        float v3 = (x.w != x.w) ? -3.0e38f : key * x.w;
        unsigned m0 = fmap(v0), m1 = fmap(v1), m2 = fmap(v2), m3 = fmap(v3);
        Vrow[4 * q + 0] = m0;
        Vrow[4 * q + 1] = m1;
        Vrow[4 * q + 2] = m2;
        Vrow[4 * q + 3] = m3;
        if (m0 > b0v) { b0v = m0; b0j = 4 * q + 0; }
        if (m1 > b0v) { b0v = m1; b0j = 4 * q + 1; }
        if (m2 > b0v) { b0v = m2; b0j = 4 * q + 2; }
        if (m3 > b0v) { b0v = m3; b0j = 4 * q + 3; }
    }
    __syncwarp();

    int mwin = 0;   // this lane's round-(lane) winner (m is warp-uniform each round)
#pragma unroll 4
    for (int r = 0; r < R; r++) {
        unsigned mx = __reduce_max_sync(FULLM, b0v);
        unsigned cand = (b0v == mx) ? (unsigned)(lane * 32 + b0j) : FULLM;
        unsigned m = __reduce_min_sync(FULLM, cand);
        if (lane == r) mwin = (int)m;

        // cooperative refill of winner column winL (branchless, every round)
        int winL = m >> 5, jwin = m & 31;
        unsigned x = V[winL * VSTR + lane];
        if (lane == jwin) {
            x = 0;
            V[winL * VSTR + jwin] = 0;   // mark consumed
        }
        unsigned mx2 = __reduce_max_sync(FULLM, x);
        unsigned jc = (x == mx2) ? (unsigned)lane : FULLM;
        unsigned j2 = __reduce_min_sync(FULLM, jc);
        if (lane == winL) { b0v = mx2; b0j = (int)j2; }
        __syncwarp();
    }

    int k = mwin >> 5, j = mwin & 31;
    int rk = __shfl_sync(FULLM, rfl, k);
    out_expand[(size_t)i * R + lane] = (float)adj[(size_t)rk * R + j];
}

__global__ void __launch_bounds__(256, 2) fused_expand_gemm(
        const int* __restrict__ rf,
        const int* __restrict__ adj,
        float* __restrict__ out_expand,
        int do_expand) {
    extern __shared__ float sm[];
    int b = blockIdx.x;
    if (!do_expand) {           // gemm-only launch
        gemm_body(b, sm);
        return;
    }
    // Bresenham role spread: exactly GEMM_BLOCKS gemm blocks among TOT_BLOCKS,
    // evenly interleaved so every SM-resident pair mixes roles.
    int gprev = (b * GEMM_BLOCKS) / TOT_BLOCKS;
    int gnext = ((b + 1) * GEMM_BLOCKS) / TOT_BLOCKS;
    if (gnext > gprev) {
        gemm_body(gprev, sm);
    } else {
        expand_body(b - gprev, rf, adj, out_expand, (unsigned*)sm);
    }
}

// ---------------- kernel 5: batchnorm + relu -> out (float4) ----------------
__global__ void bn_kernel(const float* __restrict__ gamma,
                          const float* __restrict__ beta,
                          float* __restrict__ out) {
    int idx4 = blockIdx.x * blockDim.x + threadIdx.x;
    if (idx4 >= N_NODES * F / 4) return;
    int c = (idx4 * 4) & (F - 1);
    const float invn = 1.0f / (float)N_NODES;
    float4 x = *(const float4*)(g_fin + (size_t)idx4 * 4);
    float4 y;
    {
        float mean = g_colsum[c + 0] * invn;
        float var = g_colsumsq[c + 0] * invn - mean * mean;
        y.x = fmaxf(gamma[c + 0] * (x.x - mean) * rsqrtf(var + BN_EPS) + beta[c + 0], 0.0f);
    }
    {
        float mean = g_colsum[c + 1] * invn;
        float var = g_colsumsq[c + 1] * invn - mean * mean;
        y.y = fmaxf(gamma[c + 1] * (x.y - mean) * rsqrtf(var + BN_EPS) + beta[c + 1], 0.0f);
    }
    {
        float mean = g_colsum[c + 2] * invn;
        float var = g_colsumsq[c + 2] * invn - mean * mean;
        y.z = fmaxf(gamma[c + 2] * (x.z - mean) * rsqrtf(var + BN_EPS) + beta[c + 2], 0.0f);
    }
    {
        float mean = g_colsum[c + 3] * invn;
        float var = g_colsumsq[c + 3] * invn - mean * mean;
        y.w = fmaxf(gamma[c + 3] * (x.w - mean) * rsqrtf(var + BN_EPS) + beta[c + 3], 0.0f);
    }
    *(float4*)(out + (size_t)idx4 * 4) = y;
}

// ---------------- launch ----------------
extern "C" void kernel_launch(void* const* d_in, const int* in_sizes, int n_in,
                              void* d_out, int out_size) {
    const float* input = (const float*)d_in[0];
    const int*   rf    = (const int*)d_in[1];
    const int*   adj   = (const int*)d_in[2];
    const float* W     = (const float*)d_in[3];
    const float* Wk    = (const float*)d_in[4];
    const float* Wq    = (const float*)d_in[5];
    const float* gamma = (const float*)d_in[6];
    const float* beta  = (const float*)d_in[7];
    float* out = (float*)d_out;

    static bool attr_done = false;
    if (!attr_done) {
        cudaFuncSetAttribute(fused_expand_gemm,
                             cudaFuncAttributeMaxDynamicSharedMemorySize, FUSED_SMEM);
        attr_done = true;
    }

    bool full_out = (out_size >= N_NODES * F + 2 * N_NODES * R);
    float* out_rf = full_out ? (out + N_NODES * F) : nullptr;
    float* out_ex = full_out ? (out + N_NODES * F + N_NODES * R) : nullptr;

    kq_kernel<<<(N_NODES * 32 + 255) / 256, 256>>>(input, Wk, Wq);      // 0
    qa_kernel<<<(N_NODES * R + 255) / 256, 256>>>(adj, W, rf, out_rf);  // 1
    agg_kernel<<<(N_NODES * 32 + 255) / 256, 256>>>(input, rf);         // 2
    int nblk = full_out ? TOT_BLOCKS : GEMM_BLOCKS;
    fused_expand_gemm<<<nblk, 256, FUSED_SMEM>>>(rf, adj, out_ex,       // 3 (profiled)
                                                 full_out ? 1 : 0);
    bn_kernel<<<(N_NODES * F / 4 + 255) / 256, 256>>>(gamma, beta, out); // 4
}

// round 11
// speedup vs baseline: 1.0295x; 1.0295x over previous
#include <cuda_runtime.h>
#include <cuda_fp16.h>

#define N_NODES 20000
#define F 256
#define R 32
#define NEI2 (R * R)
#define BN_EPS 1e-5f
#define FULLM 0xffffffffu

// ---------------- scratch (no allocations allowed) ----------------
__device__ float g_K[N_NODES];
__device__ float g_Q[N_NODES];
__device__ __align__(16) float g_QA[(size_t)N_NODES * R];    // Q[adj[c][j]] (NaN if masked)
__device__ __align__(16) unsigned short g_inh[(size_t)N_NODES * F];  // fp16 copy of input
__device__ __align__(16) float g_agg[(size_t)N_NODES * F];   // aggregated rows, tf32-rounded
__device__ __align__(16) float g_Wt[F * F];                  // W, tf32-rounded
__device__ float g_fin[(size_t)N_NODES * F];   // pre-BN final_h
__device__ float g_colsum[F];
__device__ float g_colsumsq[F];

__device__ __forceinline__ float nan_f()  { return __int_as_float(0x7fffffffu); }

__device__ __forceinline__ unsigned f2tf32(float x) {
    unsigned r;
    asm("cvt.rna.tf32.f32 %0, %1;" : "=r"(r) : "f"(x));
    return r;
}
__device__ __forceinline__ float tf32r(float x) { return __uint_as_float(f2tf32(x)); }

// order-preserving float -> uint map (never 0 for non-NaN input)
__device__ __forceinline__ unsigned fmap(float v) {
    unsigned b = __float_as_uint(v);
    return (b & 0x80000000u) ? ~b : (b | 0x80000000u);
}

__device__ __forceinline__ void cp16(unsigned dst, const void* src, int sz) {
    asm volatile("cp.async.cg.shared.global [%0], [%1], 16, %2;"
                 :: "r"(dst), "l"(src), "r"(sz));
}

// ---------------- side stream + fork/join events (created pre-capture, no device mem APIs) ----
struct GraphStreams {
    cudaStream_t s2 = 0;
    cudaEvent_t e1 = 0, e2 = 0;
    bool ok = false;
    GraphStreams() {
        ok = (cudaStreamCreateWithFlags(&s2, cudaStreamNonBlocking) == cudaSuccess)
          && (cudaEventCreateWithFlags(&e1, cudaEventDisableTiming) == cudaSuccess)
          && (cudaEventCreateWithFlags(&e2, cudaEventDisableTiming) == cudaSuccess);
        if (!ok) s2 = 0;   // degrade to serial on the null stream
    }
};
static GraphStreams g_gs;

// ---------------- kernel 1: Key/Query scalars + fp16 copy + BN-acc zeroing ----------------
__global__ void kq_kernel(const float* __restrict__ input,
                          const float* __restrict__ Wk,
                          const float* __restrict__ Wq) {
    if (blockIdx.x == 0) {
        int t = threadIdx.x;
        if (t < F) { g_colsum[t] = 0.0f; g_colsumsq[t] = 0.0f; }
    }
    int warp = (blockIdx.x * blockDim.x + threadIdx.x) >> 5;
    int lane = threadIdx.x & 31;
    if (warp >= N_NODES) return;
    const float4* row = (const float4*)(input + (size_t)warp * F);
    const float4* wk4 = (const float4*)Wk;
    const float4* wq4 = (const float4*)Wq;
    float4 x0 = row[lane];
    float4 x1 = row[32 + lane];
    float sk, sq;
    {
        float4 a = wk4[lane], a1 = wk4[32 + lane];
        sk = x0.x * a.x + x0.y * a.y + x0.z * a.z + x0.w * a.w
           + x1.x * a1.x + x1.y * a1.y + x1.z * a1.z + x1.w * a1.w;
        float4 b = wq4[lane], b1 = wq4[32 + lane];
        sq = x0.x * b.x + x0.y * b.y + x0.z * b.z + x0.w * b.w
           + x1.x * b1.x + x1.y * b1.y + x1.z * b1.z + x1.w * b1.w;
    }
    {
        __half2 h0 = __float22half2_rn(make_float2(x0.x, x0.y));
        __half2 h1 = __float22half2_rn(make_float2(x0.z, x0.w));
        __half2 h2 = __float22half2_rn(make_float2(x1.x, x1.y));
        __half2 h3 = __float22half2_rn(make_float2(x1.z, x1.w));
        uint2 p0 = make_uint2(*(unsigned*)&h0, *(unsigned*)&h1);
        uint2 p1 = make_uint2(*(unsigned*)&h2, *(unsigned*)&h3);
        *(uint2*)(g_inh + (size_t)warp * F + 4 * lane)       = p0;
        *(uint2*)(g_inh + (size_t)warp * F + 128 + 4 * lane) = p1;
    }
#pragma unroll
    for (int o = 16; o; o >>= 1) {
        sk += __shfl_xor_sync(FULLM, sk, o);
        sq += __shfl_xor_sync(FULLM, sq, o);
    }
    if (lane == 0) { g_K[warp] = sk; g_Q[warp] = sq; }
}

// ---------------- kernel 1b: QA table + W tf32 conversion + rf copy ----------------
__global__ void qa_kernel(const int* __restrict__ adj,
                          const float* __restrict__ W,
                          const int* __restrict__ rf,
                          float* __restrict__ out_rf) {
    int idx = blockIdx.x * blockDim.x + threadIdx.x;
    if (idx < F * F) g_Wt[idx] = tf32r(W[idx]);
    if (idx >= N_NODES * R) return;
    int id = adj[idx];
    g_QA[idx] = (id == N_NODES - 1) ? nan_f() : g_Q[id];
    if (out_rf) out_rf[idx] = (float)rf[idx];
}

// ---------------- kernel 2: attention softmax + fp16 aggregation (tf32-rounded out) ----------------
__global__ void agg_kernel(const float* __restrict__ input,
                           const int* __restrict__ rf) {
    int gw = (blockIdx.x * blockDim.x + threadIdx.x) >> 5;
    int lane = threadIdx.x & 31;
    if (gw >= N_NODES) return;

    int rid = rf[gw * R + lane];
    float v = (rid == N_NODES - 1) ? -3.0e38f : g_K[gw] * g_Q[rid];
    float m = v;
#pragma unroll
    for (int o = 16; o; o >>= 1) m = fmaxf(m, __shfl_xor_sync(FULLM, m, o));
    float e = expf(v - m);
    float s = e;
#pragma unroll
    for (int o = 16; o; o >>= 1) s += __shfl_xor_sync(FULLM, s, o);
    float wgt = e / s;

    const float4* own = (const float4*)(input + (size_t)gw * F);
    float4 o0 = own[lane * 2];
    float4 o1 = own[lane * 2 + 1];
    float acc[8] = {o0.x, o0.y, o0.z, o0.w, o1.x, o1.y, o1.z, o1.w};

#pragma unroll 4
    for (int j = 0; j < R; j++) {
        float wj = __shfl_sync(FULLM, wgt, j);
        int id = __shfl_sync(FULLM, rid, j);
        if (wj != 0.0f) {
            uint4 h = *(const uint4*)(g_inh + (size_t)id * F + lane * 8);
            float2 f;
            f = __half22float2(*(__half2*)&h.x); acc[0] += wj * f.x; acc[1] += wj * f.y;
            f = __half22float2(*(__half2*)&h.y); acc[2] += wj * f.x; acc[3] += wj * f.y;
            f = __half22float2(*(__half2*)&h.z); acc[4] += wj * f.x; acc[5] += wj * f.y;
            f = __half22float2(*(__half2*)&h.w); acc[6] += wj * f.x; acc[7] += wj * f.y;
        }
    }
    float4* dst = (float4*)(g_agg + (size_t)gw * F);
    dst[lane * 2]     = make_float4(tf32r(acc[0]), tf32r(acc[1]), tf32r(acc[2]), tf32r(acc[3]));
    dst[lane * 2 + 1] = make_float4(tf32r(acc[4]), tf32r(acc[5]), tf32r(acc[6]), tf32r(acc[7]));
}

// ---------------- kernel 7: 2-hop expansion, exact stable top-32 of 1024 (R7-proven) ----------------
#define EWPB 8
#define VSTR 33
__global__ void expand_kernel(const int* __restrict__ rf,
                              const int* __restrict__ adj,
                              float* __restrict__ out_expand) {
    __shared__ unsigned V[EWPB][R * VSTR];
    int w = threadIdx.x >> 5;
    int lane = threadIdx.x & 31;
    int i = blockIdx.x * EWPB + w;
    if (i >= N_NODES) return;

    float key = g_K[i];
    int rfl = rf[i * R + lane];

    // load own QA row (8 x float4); per-lane top-1 (smallest j among equals)
    unsigned b0v = 0;
    int b0j = 0;
    const float4* qrow = (const float4*)(g_QA + (size_t)rfl * R);
    unsigned* Vrow = &V[w][lane * VSTR];
#pragma unroll
    for (int q = 0; q < 8; q++) {
        float4 x = qrow[q];
        float v0 = (x.x != x.x) ? -3.0e38f : key * x.x;
        float v1 = (x.y != x.y) ? -3.0e38f : key * x.y;
        float v2 = (x.z != x.z) ? -3.0e38f : key * x.z;
        float v3 = (x.w != x.w) ? -3.0e38f : key * x.w;
        unsigned m0 = fmap(v0), m1 = fmap(v1), m2 = fmap(v2), m3 = fmap(v3);
        Vrow[4 * q + 0] = m0;
        Vrow[4 * q + 1] = m1;
        Vrow[4 * q + 2] = m2;
        Vrow[4 * q + 3] = m3;
        if (m0 > b0v) { b0v = m0; b0j = 4 * q + 0; }
        if (m1 > b0v) { b0v = m1; b0j = 4 * q + 1; }
        if (m2 > b0v) { b0v = m2; b0j = 4 * q + 2; }
        if (m3 > b0v) { b0v = m3; b0j = 4 * q + 3; }
    }
    __syncwarp();

    int mwin = 0;   // this lane's round-(lane) winner (m is warp-uniform each round)
#pragma unroll 4
    for (int r = 0; r < R; r++) {
        unsigned mx = __reduce_max_sync(FULLM, b0v);
        unsigned cand = (b0v == mx) ? (unsigned)(lane * 32 + b0j) : FULLM;
        unsigned m = __reduce_min_sync(FULLM, cand);
        if (lane == r) mwin = (int)m;

        // cooperative refill of winner column winL (branchless, every round)
        int winL = m >> 5, jwin = m & 31;
        unsigned x = V[w][winL * VSTR + lane];
        if (lane == jwin) {
            x = 0;
            V[w][winL * VSTR + jwin] = 0;   // mark consumed
        }
        unsigned mx2 = __reduce_max_sync(FULLM, x);
        unsigned jc = (x == mx2) ? (unsigned)lane : FULLM;
        unsigned j2 = __reduce_min_sync(FULLM, jc);
        if (lane == winL) { b0v = mx2; b0j = (int)j2; }
        __syncwarp();
    }

    int k = mwin >> 5, j = mwin & 31;
    int rk = __shfl_sync(FULLM, rfl, k);
    out_expand[(size_t)i * R + lane] = (float)adj[(size_t)rk * R + j];
}

// ---------------- kernel 3: tf32 MMA GEMM (cp.async 2-stage) + fused column sums ----------------
#define GBM 128
#define GBN 128
#define GKC 32
#define ASTR 36
#define BSTR 136
#define ASZ (GBM * ASTR)
#define BSZ (GKC * BSTR)
#define STG (ASZ + BSZ)
#define GEMM_SMEM (2 * STG * 4)
#define NKT (F / GKC)

__global__ void __launch_bounds__(256, 2) gemm_kernel() {
    extern __shared__ float sm[];
    unsigned smb = (unsigned)__cvta_generic_to_shared(sm);
    int bm = blockIdx.x * GBM;
    int bn = blockIdx.y * GBN;
    int t = threadIdx.x;
    int lane = t & 31, warp = t >> 5;
    int warp_m = warp >> 1, warp_n = warp & 1;
    int g = lane >> 2, tg = lane & 3;
    int m0 = warp_m * 32, n0 = warp_n * 64;

    int arow = t >> 1, akc = (t & 1) * 16;
    int bk = t >> 3, bc = (t & 7) * 16;
    int gr = bm + arow;
    int asz = (gr < N_NODES) ? 16 : 0;
    const float* asrc = g_agg + (size_t)(gr < N_NODES ? gr : 0) * F + akc;
    const float* bsrc = g_Wt + (size_t)bk * F + bn + bc;

    float acc[2][8][4];
#pragma unroll
    for (int mt = 0; mt < 2; mt++)
#pragma unroll
        for (int nt = 0; nt < 8; nt++)
#pragma unroll
            for (int c = 0; c < 4; c++) acc[mt][nt][c] = 0.0f;

    auto issue = [&](int stage, int kt) {
        unsigned ab = smb + (stage * STG + arow * ASTR + akc) * 4;
        const float* as = asrc + kt;
#pragma unroll
        for (int q = 0; q < 4; q++) cp16(ab + q * 16, as + q * 4, asz);
        unsigned bb = smb + (stage * STG + ASZ + bk * BSTR + bc) * 4;
        const float* bs = bsrc + (size_t)kt * F;
#pragma unroll
        for (int q = 0; q < 4; q++) cp16(bb + q * 16, bs + q * 4, 16);
        asm volatile("cp.async.commit_group;");
    };

    issue(0, 0);

    for (int s = 0; s < NKT; s++) {
        if (s + 1 < NKT) {
            issue((s + 1) & 1, (s + 1) * GKC);
            asm volatile("cp.async.wait_group 1;");
        } else {
            asm volatile("cp.async.wait_group 0;");
        }
        __syncthreads();

        const unsigned* As = (const unsigned*)(sm + (s & 1) * STG);
        const unsigned* Bs = (const unsigned*)(sm + (s & 1) * STG + ASZ);
#pragma unroll
        for (int kk = 0; kk < 4; kk++) {
            int k8 = kk * 8;
            unsigned af[2][4];
#pragma unroll
            for (int mt = 0; mt < 2; mt++) {
                int r0 = m0 + mt * 16 + g;
                af[mt][0] = As[r0 * ASTR + k8 + tg];
                af[mt][1] = As[(r0 + 8) * ASTR + k8 + tg];
                af[mt][2] = As[r0 * ASTR + k8 + tg + 4];
                af[mt][3] = As[(r0 + 8) * ASTR + k8 + tg + 4];
            }
            unsigned bf[8][2];
#pragma unroll
            for (int nt = 0; nt < 8; nt++) {
                bf[nt][0] = Bs[(k8 + tg) * BSTR + n0 + nt * 8 + g];
                bf[nt][1] = Bs[(k8 + tg + 4) * BSTR + n0 + nt * 8 + g];
            }
#pragma unroll
            for (int mt = 0; mt < 2; mt++)
#pragma unroll
                for (int nt = 0; nt < 8; nt++) {
                    asm volatile(
                        "mma.sync.aligned.m16n8k8.row.col.f32.tf32.tf32.f32 "
                        "{%0,%1,%2,%3}, {%4,%5,%6,%7}, {%8,%9}, {%0,%1,%2,%3};"
                        : "+f"(acc[mt][nt][0]), "+f"(acc[mt][nt][1]),
                          "+f"(acc[mt][nt][2]), "+f"(acc[mt][nt][3])
                        : "r"(af[mt][0]), "r"(af[mt][1]), "r"(af[mt][2]), "r"(af[mt][3]),
                          "r"(bf[nt][0]), "r"(bf[nt][1]));
                }
        }
        __syncthreads();
    }

    // store C + fused column sum / sum-of-squares (OOB rows are exact zeros)
#pragma unroll
    for (int mt = 0; mt < 2; mt++) {
        int row0 = bm + m0 + mt * 16 + g;
        int row1 = row0 + 8;
#pragma unroll
        for (int nt = 0; nt < 8; nt++) {
            int col = bn + n0 + nt * 8 + 2 * tg;
            if (row0 < N_NODES)
                *(float2*)(g_fin + (size_t)row0 * F + col) =
                    make_float2(acc[mt][nt][0], acc[mt][nt][1]);
            if (row1 < N_NODES)
                *(float2*)(g_fin + (size_t)row1 * F + col) =
                    make_float2(acc[mt][nt][2], acc[mt][nt][3]);
        }
    }
#pragma unroll
    for (int nt = 0; nt < 8; nt++) {
        float s0 = acc[0][nt][0] + acc[0][nt][2] + acc[1][nt][0] + acc[1][nt][2];
        float s1 = acc[0][nt][1] + acc[0][nt][3] + acc[1][nt][1] + acc[1][nt][3];
        float q0 = acc[0][nt][0] * acc[0][nt][0] + acc[0][nt][2] * acc[0][nt][2]
                 + acc[1][nt][0] * acc[1][nt][0] + acc[1][nt][2] * acc[1][nt][2];
        float q1 = acc[0][nt][1] * acc[0][nt][1] + acc[0][nt][3] * acc[0][nt][3]
                 + acc[1][nt][1] * acc[1][nt][1] + acc[1][nt][3] * acc[1][nt][3];
#pragma unroll
        for (int o = 4; o <= 16; o <<= 1) {
            s0 += __shfl_xor_sync(FULLM, s0, o);
            s1 += __shfl_xor_sync(FULLM, s1, o);
            q0 += __shfl_xor_sync(FULLM, q0, o);
            q1 += __shfl_xor_sync(FULLM, q1, o);
        }
        if (lane < 4) {
            int col = bn + n0 + nt * 8 + 2 * tg;
            atomicAdd(&g_colsum[col], s0);
            atomicAdd(&g_colsum[col + 1], s1);
            atomicAdd(&g_colsumsq[col], q0);
            atomicAdd(&g_colsumsq[col + 1], q1);
        }
    }
}

// ---------------- kernel 5: batchnorm + relu -> out (float4) ----------------
__global__ void bn_kernel(const float* __restrict__ gamma,
                          const float* __restrict__ beta,
                          float* __restrict__ out) {
    int idx4 = blockIdx.x * blockDim.x + threadIdx.x;
    if (idx4 >= N_NODES * F / 4) return;
    int c = (idx4 * 4) & (F - 1);
    const float invn = 1.0f / (float)N_NODES;
    float4 x = *(const float4*)(g_fin + (size_t)idx4 * 4);
    float4 y;
    {
        float mean = g_colsum[c + 0] * invn;
        float var = g_colsumsq[c + 0] * invn - mean * mean;
        y.x = fmaxf(gamma[c + 0] * (x.x - mean) * rsqrtf(var + BN_EPS) + beta[c + 0], 0.0f);
    }
    {
        float mean = g_colsum[c + 1] * invn;
        float var = g_colsumsq[c + 1] * invn - mean * mean;
        y.y = fmaxf(gamma[c + 1] * (x.y - mean) * rsqrtf(var + BN_EPS) + beta[c + 1], 0.0f);
    }
    {
        float mean = g_colsum[c + 2] * invn;
        float var = g_colsumsq[c + 2] * invn - mean * mean;
        y.z = fmaxf(gamma[c + 2] * (x.z - mean) * rsqrtf(var + BN_EPS) + beta[c + 2], 0.0f);
    }
    {
        float mean = g_colsum[c + 3] * invn;
        float var = g_colsumsq[c + 3] * invn - mean * mean;
        y.w = fmaxf(gamma[c + 3] * (x.w - mean) * rsqrtf(var + BN_EPS) + beta[c + 3], 0.0f);
    }
    *(float4*)(out + (size_t)idx4 * 4) = y;
}

// ---------------- launch: parallel graph via event fork/join ----------------
extern "C" void kernel_launch(void* const* d_in, const int* in_sizes, int n_in,
                              void* d_out, int out_size) {
    const float* input = (const float*)d_in[0];
    const int*   rf    = (const int*)d_in[1];
    const int*   adj   = (const int*)d_in[2];
    const float* W     = (const float*)d_in[3];
    const float* Wk    = (const float*)d_in[4];
    const float* Wq    = (const float*)d_in[5];
    const float* gamma = (const float*)d_in[6];
    const float* beta  = (const float*)d_in[7];
    float* out = (float*)d_out;

    static bool attr_done = false;
    if (!attr_done) {
        cudaFuncSetAttribute(gemm_kernel,
                             cudaFuncAttributeMaxDynamicSharedMemorySize, GEMM_SMEM);
        attr_done = true;
    }

    bool full_out = (out_size >= N_NODES * F + 2 * N_NODES * R);
    float* out_rf = full_out ? (out + N_NODES * F) : nullptr;
    float* out_ex = full_out ? (out + N_NODES * F + N_NODES * R) : nullptr;
    bool fork = full_out && g_gs.ok;

    kq_kernel<<<(N_NODES * 32 + 255) / 256, 256>>>(input, Wk, Wq);
    qa_kernel<<<(N_NODES * R + 255) / 256, 256>>>(adj, W, rf, out_rf);

    if (full_out) {
        if (fork) {
            // fork: expand runs on side stream, overlapping agg+gemm on the main stream
            cudaEventRecord(g_gs.e1, 0);
            cudaStreamWaitEvent(g_gs.s2, g_gs.e1, 0);
            expand_kernel<<<(N_NODES + EWPB - 1) / EWPB, EWPB * 32, 0, g_gs.s2>>>(
                rf, adj, out_ex);
            cudaEventRecord(g_gs.e2, g_gs.s2);
        } else {
            expand_kernel<<<(N_NODES + EWPB - 1) / EWPB, EWPB * 32>>>(rf, adj, out_ex);
        }
    }

    agg_kernel<<<(N_NODES * 32 + 255) / 256, 256>>>(input, rf);
    dim3 gg((N_NODES + GBM - 1) / GBM, F / GBN);
    gemm_kernel<<<gg, 256, GEMM_SMEM>>>();

    if (fork) cudaStreamWaitEvent(0, g_gs.e2, 0);   // join before final output pass
    bn_kernel<<<(N_NODES * F / 4 + 255) / 256, 256>>>(gamma, beta, out);
}

// round 12
// speedup vs baseline: 1.1491x; 1.1162x over previous
#include <cuda_runtime.h>
#include <cuda_fp16.h>

#define N_NODES 20000
#define F 256
#define R 32
#define NEI2 (R * R)
#define BN_EPS 1e-5f
#define FULLM 0xffffffffu

// ---------------- scratch (no allocations allowed) ----------------
__device__ float g_K[N_NODES];
__device__ float g_Q[N_NODES];
__device__ __align__(16) float g_QA[(size_t)N_NODES * R];    // Q[adj[c][j]] (NaN if masked)
__device__ __align__(16) unsigned short g_inh[(size_t)N_NODES * F];   // fp16 input copy
__device__ __align__(16) unsigned short g_aggh[(size_t)N_NODES * F];  // aggregated rows, fp16
__device__ __align__(16) unsigned short g_Wth[F * F];                 // W^T (n-major), fp16
__device__ float g_fin[(size_t)N_NODES * F];   // pre-BN final_h
__device__ float g_colsum[F];
__device__ float g_colsumsq[F];

__device__ __forceinline__ float nan_f()  { return __int_as_float(0x7fffffffu); }

// order-preserving float -> uint map (never 0 for non-NaN input)
__device__ __forceinline__ unsigned fmap(float v) {
    unsigned b = __float_as_uint(v);
    return (b & 0x80000000u) ? ~b : (b | 0x80000000u);
}

__device__ __forceinline__ void cp16(unsigned dst, const void* src, int sz) {
    asm volatile("cp.async.cg.shared.global [%0], [%1], 16, %2;"
                 :: "r"(dst), "l"(src), "r"(sz));
}

// ---------------- side stream + fork/join events (created pre-capture, no device mem APIs) ----
struct GraphStreams {
    cudaStream_t s2 = 0;
    cudaEvent_t e1 = 0, e2 = 0;
    bool ok = false;
    GraphStreams() {
        ok = (cudaStreamCreateWithFlags(&s2, cudaStreamNonBlocking) == cudaSuccess)
          && (cudaEventCreateWithFlags(&e1, cudaEventDisableTiming) == cudaSuccess)
          && (cudaEventCreateWithFlags(&e2, cudaEventDisableTiming) == cudaSuccess);
        if (!ok) s2 = 0;
    }
};
static GraphStreams g_gs;

// ---------------- kernel 1: Key/Query scalars + fp16 copy + BN-acc zeroing ----------------
__global__ void kq_kernel(const float* __restrict__ input,
                          const float* __restrict__ Wk,
                          const float* __restrict__ Wq) {
    if (blockIdx.x == 0) {
        int t = threadIdx.x;
        if (t < F) { g_colsum[t] = 0.0f; g_colsumsq[t] = 0.0f; }
    }
    int warp = (blockIdx.x * blockDim.x + threadIdx.x) >> 5;
    int lane = threadIdx.x & 31;
    if (warp >= N_NODES) return;
    const float4* row = (const float4*)(input + (size_t)warp * F);
    const float4* wk4 = (const float4*)Wk;
    const float4* wq4 = (const float4*)Wq;
    float4 x0 = row[lane];
    float4 x1 = row[32 + lane];
    float sk, sq;
    {
        float4 a = wk4[lane], a1 = wk4[32 + lane];
        sk = x0.x * a.x + x0.y * a.y + x0.z * a.z + x0.w * a.w
           + x1.x * a1.x + x1.y * a1.y + x1.z * a1.z + x1.w * a1.w;
        float4 b = wq4[lane], b1 = wq4[32 + lane];
        sq = x0.x * b.x + x0.y * b.y + x0.z * b.z + x0.w * b.w
           + x1.x * b1.x + x1.y * b1.y + x1.z * b1.z + x1.w * b1.w;
    }
    {
        __half2 h0 = __float22half2_rn(make_float2(x0.x, x0.y));
        __half2 h1 = __float22half2_rn(make_float2(x0.z, x0.w));
        __half2 h2 = __float22half2_rn(make_float2(x1.x, x1.y));
        __half2 h3 = __float22half2_rn(make_float2(x1.z, x1.w));
        uint2 p0 = make_uint2(*(unsigned*)&h0, *(unsigned*)&h1);
        uint2 p1 = make_uint2(*(unsigned*)&h2, *(unsigned*)&h3);
        *(uint2*)(g_inh + (size_t)warp * F + 4 * lane)       = p0;
        *(uint2*)(g_inh + (size_t)warp * F + 128 + 4 * lane) = p1;
    }
#pragma unroll
    for (int o = 16; o; o >>= 1) {
        sk += __shfl_xor_sync(FULLM, sk, o);
        sq += __shfl_xor_sync(FULLM, sq, o);
    }
    if (lane == 0) { g_K[warp] = sk; g_Q[warp] = sq; }
}

// ---------------- kernel 1b: QA table + W^T fp16 conversion + rf copy ----------------
__global__ void qa_kernel(const int* __restrict__ adj,
                          const float* __restrict__ W,
                          const int* __restrict__ rf,
                          float* __restrict__ out_rf) {
    int idx = blockIdx.x * blockDim.x + threadIdx.x;
    if (idx < F * F) {
        int n = idx >> 8, k = idx & (F - 1);
        g_Wth[idx] = __half_as_ushort(__float2half_rn(W[k * F + n]));
    }
    if (idx >= N_NODES * R) return;
    int id = adj[idx];
    g_QA[idx] = (id == N_NODES - 1) ? nan_f() : g_Q[id];
    if (out_rf) out_rf[idx] = (float)rf[idx];
}

// ---------------- kernel 2: attention softmax + fp16 aggregation (fp16 out) ----------------
__global__ void agg_kernel(const float* __restrict__ input,
                           const int* __restrict__ rf) {
    int gw = (blockIdx.x * blockDim.x + threadIdx.x) >> 5;
    int lane = threadIdx.x & 31;
    if (gw >= N_NODES) return;

    int rid = rf[gw * R + lane];
    float v = (rid == N_NODES - 1) ? -3.0e38f : g_K[gw] * g_Q[rid];
    float m = v;
#pragma unroll
    for (int o = 16; o; o >>= 1) m = fmaxf(m, __shfl_xor_sync(FULLM, m, o));
    float e = expf(v - m);
    float s = e;
#pragma unroll
    for (int o = 16; o; o >>= 1) s += __shfl_xor_sync(FULLM, s, o);
    float wgt = e / s;

    const float4* own = (const float4*)(input + (size_t)gw * F);
    float4 o0 = own[lane * 2];
    float4 o1 = own[lane * 2 + 1];
    float acc[8] = {o0.x, o0.y, o0.z, o0.w, o1.x, o1.y, o1.z, o1.w};

#pragma unroll 4
    for (int j = 0; j < R; j++) {
        float wj = __shfl_sync(FULLM, wgt, j);
        int id = __shfl_sync(FULLM, rid, j);
        if (wj != 0.0f) {
            uint4 h = *(const uint4*)(g_inh + (size_t)id * F + lane * 8);
            float2 f;
            f = __half22float2(*(__half2*)&h.x); acc[0] += wj * f.x; acc[1] += wj * f.y;
            f = __half22float2(*(__half2*)&h.y); acc[2] += wj * f.x; acc[3] += wj * f.y;
            f = __half22float2(*(__half2*)&h.z); acc[4] += wj * f.x; acc[5] += wj * f.y;
            f = __half22float2(*(__half2*)&h.w); acc[6] += wj * f.x; acc[7] += wj * f.y;
        }
    }
    __half2 r0 = __float22half2_rn(make_float2(acc[0], acc[1]));
    __half2 r1 = __float22half2_rn(make_float2(acc[2], acc[3]));
    __half2 r2 = __float22half2_rn(make_float2(acc[4], acc[5]));
    __half2 r3 = __float22half2_rn(make_float2(acc[6], acc[7]));
    uint4 p = make_uint4(*(unsigned*)&r0, *(unsigned*)&r1, *(unsigned*)&r2, *(unsigned*)&r3);
    *(uint4*)(g_aggh + (size_t)gw * F + lane * 8) = p;
}

// ---------------- kernel 7: 2-hop expansion, exact stable top-32 of 1024 (R7-proven) ----------------
#define EWPB 8
#define VSTR 33
__global__ void expand_kernel(const int* __restrict__ rf,
                              const int* __restrict__ adj,
                              float* __restrict__ out_expand) {
    __shared__ unsigned V[EWPB][R * VSTR];
    int w = threadIdx.x >> 5;
    int lane = threadIdx.x & 31;
    int i = blockIdx.x * EWPB + w;
    if (i >= N_NODES) return;

    float key = g_K[i];
    int rfl = rf[i * R + lane];

    unsigned b0v = 0;
    int b0j = 0;
    const float4* qrow = (const float4*)(g_QA + (size_t)rfl * R);
    unsigned* Vrow = &V[w][lane * VSTR];
#pragma unroll
    for (int q = 0; q < 8; q++) {
        float4 x = qrow[q];
        float v0 = (x.x != x.x) ? -3.0e38f : key * x.x;
        float v1 = (x.y != x.y) ? -3.0e38f : key * x.y;
        float v2 = (x.z != x.z) ? -3.0e38f : key * x.z;
        float v3 = (x.w != x.w) ? -3.0e38f : key * x.w;
        unsigned m0 = fmap(v0), m1 = fmap(v1), m2 = fmap(v2), m3 = fmap(v3);
        Vrow[4 * q + 0] = m0;
        Vrow[4 * q + 1] = m1;
        Vrow[4 * q + 2] = m2;
        Vrow[4 * q + 3] = m3;
        if (m0 > b0v) { b0v = m0; b0j = 4 * q + 0; }
        if (m1 > b0v) { b0v = m1; b0j = 4 * q + 1; }
        if (m2 > b0v) { b0v = m2; b0j = 4 * q + 2; }
        if (m3 > b0v) { b0v = m3; b0j = 4 * q + 3; }
    }
    __syncwarp();

    int mwin = 0;
#pragma unroll 4
    for (int r = 0; r < R; r++) {
        unsigned mx = __reduce_max_sync(FULLM, b0v);
        unsigned cand = (b0v == mx) ? (unsigned)(lane * 32 + b0j) : FULLM;
        unsigned m = __reduce_min_sync(FULLM, cand);
        if (lane == r) mwin = (int)m;

        int winL = m >> 5, jwin = m & 31;
        unsigned x = V[w][winL * VSTR + lane];
        if (lane == jwin) {
            x = 0;
            V[w][winL * VSTR + jwin] = 0;
        }
        unsigned mx2 = __reduce_max_sync(FULLM, x);
        unsigned jc = (x == mx2) ? (unsigned)lane : FULLM;
        unsigned j2 = __reduce_min_sync(FULLM, jc);
        if (lane == winL) { b0v = mx2; b0j = (int)j2; }
        __syncwarp();
    }

    int k = mwin >> 5, j = mwin & 31;
    int rk = __shfl_sync(FULLM, rfl, k);
    out_expand[(size_t)i * R + lane] = (float)adj[(size_t)rk * R + j];
}

// ---------------- kernel 3: fp16 MMA GEMM (cp.async 2-stage, K-chunk 64) + fused col sums ----
// Block 128x128, 8 warps (4x2), warp tile 32x64 = 2x8 m16n8k16.
// A and B^T tiles share the same layout: 128 rows x 32 half2, stride 36 half2 (conflict-free).
#define GBM 128
#define GBN 128
#define GKC 64
#define ASTR 36                    // stride in half2 units
#define TSZ (GBM * ASTR)           // half2 per tile = 4608
#define STG (2 * TSZ)              // half2 per stage (A + B)
#define GEMM_SMEM (2 * STG * 4)    // bytes, 2 stages = 73728
#define NKT (F / GKC)              // 4

__global__ void __launch_bounds__(256, 2) gemm_kernel() {
    extern __shared__ unsigned sm[];           // half2 units
    unsigned smb = (unsigned)__cvta_generic_to_shared(sm);
    int bm = blockIdx.x * GBM;
    int bn = blockIdx.y * GBN;
    int t = threadIdx.x;
    int lane = t & 31, warp = t >> 5;
    int warp_m = warp >> 1, warp_n = warp & 1;
    int g = lane >> 2, tg = lane & 3;
    int m0 = warp_m * 32, n0 = warp_n * 64;

    int arow = t >> 1;                         // 0..127 (same for A rows and B n-rows)
    int ah = (t & 1) * 32;                     // half offset within 64-half row chunk
    int gr = bm + arow;
    int asz = (gr < N_NODES) ? 16 : 0;
    const unsigned short* asrc = g_aggh + (size_t)(gr < N_NODES ? gr : 0) * F + ah;
    const unsigned short* bsrc = g_Wth + (size_t)(bn + arow) * F + ah;

    float acc[2][8][4];
#pragma unroll
    for (int mt = 0; mt < 2; mt++)
#pragma unroll
        for (int nt = 0; nt < 8; nt++)
#pragma unroll
            for (int c = 0; c < 4; c++) acc[mt][nt][c] = 0.0f;

    // copy one stage: A rows [bm..+127] k [kt..kt+63]; B n-rows [bn..+127] same k
    auto issue = [&](int stage, int kt) {
        unsigned ab = smb + (stage * STG + arow * ASTR + (ah >> 1)) * 4;
        const unsigned short* as = asrc + kt;
#pragma unroll
        for (int q = 0; q < 4; q++) cp16(ab + q * 16, as + q * 8, asz);
        unsigned bb = smb + (stage * STG + TSZ + arow * ASTR + (ah >> 1)) * 4;
        const unsigned short* bs = bsrc + kt;
#pragma unroll
        for (int q = 0; q < 4; q++) cp16(bb + q * 16, bs + q * 8, 16);
        asm volatile("cp.async.commit_group;");
    };

    issue(0, 0);

    for (int s = 0; s < NKT; s++) {
        if (s + 1 < NKT) {
            issue((s + 1) & 1, (s + 1) * GKC);
            asm volatile("cp.async.wait_group 1;");
        } else {
            asm volatile("cp.async.wait_group 0;");
        }
        __syncthreads();

        const unsigned* As = sm + (s & 1) * STG;
        const unsigned* Bs = sm + (s & 1) * STG + TSZ;
#pragma unroll
        for (int kk = 0; kk < 4; kk++) {       // 4 k-steps of 16 within the 64-chunk
            int k2 = kk * 8;
            unsigned af[2][4];
#pragma unroll
            for (int mt = 0; mt < 2; mt++) {
                int r0 = m0 + mt * 16 + g;
                af[mt][0] = As[r0 * ASTR + k2 + tg];
                af[mt][1] = As[(r0 + 8) * ASTR + k2 + tg];
                af[mt][2] = As[r0 * ASTR + k2 + tg + 4];
                af[mt][3] = As[(r0 + 8) * ASTR + k2 + tg + 4];
            }
            unsigned bf[8][2];
#pragma unroll
            for (int nt = 0; nt < 8; nt++) {
                int nr = n0 + nt * 8 + g;
                bf[nt][0] = Bs[nr * ASTR + k2 + tg];
                bf[nt][1] = Bs[nr * ASTR + k2 + tg + 4];
            }
#pragma unroll
            for (int mt = 0; mt < 2; mt++)
#pragma unroll
                for (int nt = 0; nt < 8; nt++) {
                    asm volatile(
                        "mma.sync.aligned.m16n8k16.row.col.f32.f16.f16.f32 "
                        "{%0,%1,%2,%3}, {%4,%5,%6,%7}, {%8,%9}, {%0,%1,%2,%3};"
                        : "+f"(acc[mt][nt][0]), "+f"(acc[mt][nt][1]),
                          "+f"(acc[mt][nt][2]), "+f"(acc[mt][nt][3])
                        : "r"(af[mt][0]), "r"(af[mt][1]), "r"(af[mt][2]), "r"(af[mt][3]),
                          "r"(bf[nt][0]), "r"(bf[nt][1]));
                }
        }
        __syncthreads();
    }

    // store C + fused column sum / sum-of-squares (OOB rows are exact zeros)
#pragma unroll
    for (int mt = 0; mt < 2; mt++) {
        int row0 = bm + m0 + mt * 16 + g;
        int row1 = row0 + 8;
#pragma unroll
        for (int nt = 0; nt < 8; nt++) {
            int col = bn + n0 + nt * 8 + 2 * tg;
            if (row0 < N_NODES)
                *(float2*)(g_fin + (size_t)row0 * F + col) =
                    make_float2(acc[mt][nt][0], acc[mt][nt][1]);
            if (row1 < N_NODES)
                *(float2*)(g_fin + (size_t)row1 * F + col) =
                    make_float2(acc[mt][nt][2], acc[mt][nt][3]);
        }
    }
#pragma unroll
    for (int nt = 0; nt < 8; nt++) {
        float s0 = acc[0][nt][0] + acc[0][nt][2] + acc[1][nt][0] + acc[1][nt][2];
        float s1 = acc[0][nt][1] + acc[0][nt][3] + acc[1][nt][1] + acc[1][nt][3];
        float q0 = acc[0][nt][0] * acc[0][nt][0] + acc[0][nt][2] * acc[0][nt][2]
                 + acc[1][nt][0] * acc[1][nt][0] + acc[1][nt][2] * acc[1][nt][2];
        float q1 = acc[0][nt][1] * acc[0][nt][1] + acc[0][nt][3] * acc[0][nt][3]
                 + acc[1][nt][1] * acc[1][nt][1] + acc[1][nt][3] * acc[1][nt][3];
#pragma unroll
        for (int o = 4; o <= 16; o <<= 1) {
            s0 += __shfl_xor_sync(FULLM, s0, o);
            s1 += __shfl_xor_sync(FULLM, s1, o);
            q0 += __shfl_xor_sync(FULLM, q0, o);
            q1 += __shfl_xor_sync(FULLM, q1, o);
        }
        if (lane < 4) {
            int col = bn + n0 + nt * 8 + 2 * tg;
            atomicAdd(&g_colsum[col], s0);
            atomicAdd(&g_colsum[col + 1], s1);
            atomicAdd(&g_colsumsq[col], q0);
            atomicAdd(&g_colsumsq[col + 1], q1);
        }
    }
}

// ---------------- kernel 5: batchnorm + relu -> out (float4) ----------------
__global__ void bn_kernel(const float* __restrict__ gamma,
                          const float* __restrict__ beta,
                          float* __restrict__ out) {
    int idx4 = blockIdx.x * blockDim.x + threadIdx.x;
    if (idx4 >= N_NODES * F / 4) return;
    int c = (idx4 * 4) & (F - 1);
    const float invn = 1.0f / (float)N_NODES;
    float4 x = *(const float4*)(g_fin + (size_t)idx4 * 4);
    float4 y;
    {
        float mean = g_colsum[c + 0] * invn;
        float var = g_colsumsq[c + 0] * invn - mean * mean;
        y.x = fmaxf(gamma[c + 0] * (x.x - mean) * rsqrtf(var + BN_EPS) + beta[c + 0], 0.0f);
    }
    {
        float mean = g_colsum[c + 1] * invn;
        float var = g_colsumsq[c + 1] * invn - mean * mean;
        y.y = fmaxf(gamma[c + 1] * (x.y - mean) * rsqrtf(var + BN_EPS) + beta[c + 1], 0.0f);
    }
    {
        float mean = g_colsum[c + 2] * invn;
        float var = g_colsumsq[c + 2] * invn - mean * mean;
        y.z = fmaxf(gamma[c + 2] * (x.z - mean) * rsqrtf(var + BN_EPS) + beta[c + 2], 0.0f);
    }
    {
        float mean = g_colsum[c + 3] * invn;
        float var = g_colsumsq[c + 3] * invn - mean * mean;
        y.w = fmaxf(gamma[c + 3] * (x.w - mean) * rsqrtf(var + BN_EPS) + beta[c + 3], 0.0f);
    }
    *(float4*)(out + (size_t)idx4 * 4) = y;
}

// ---------------- launch: parallel graph via event fork/join ----------------
extern "C" void kernel_launch(void* const* d_in, const int* in_sizes, int n_in,
                              void* d_out, int out_size) {
    const float* input = (const float*)d_in[0];
    const int*   rf    = (const int*)d_in[1];
    const int*   adj   = (const int*)d_in[2];
    const float* W     = (const float*)d_in[3];
    const float* Wk    = (const float*)d_in[4];
    const float* Wq    = (const float*)d_in[5];
    const float* gamma = (const float*)d_in[6];
    const float* beta  = (const float*)d_in[7];
    float* out = (float*)d_out;

    static bool attr_done = false;
    if (!attr_done) {
        cudaFuncSetAttribute(gemm_kernel,
                             cudaFuncAttributeMaxDynamicSharedMemorySize, GEMM_SMEM);
        attr_done = true;
    }

    bool full_out = (out_size >= N_NODES * F + 2 * N_NODES * R);
    float* out_rf = full_out ? (out + N_NODES * F) : nullptr;
    float* out_ex = full_out ? (out + N_NODES * F + N_NODES * R) : nullptr;
    bool fork = full_out && g_gs.ok;

    kq_kernel<<<(N_NODES * 32 + 255) / 256, 256>>>(input, Wk, Wq);
    qa_kernel<<<(N_NODES * R + 255) / 256, 256>>>(adj, W, rf, out_rf);

    if (full_out) {
        if (fork) {
            cudaEventRecord(g_gs.e1, 0);
            cudaStreamWaitEvent(g_gs.s2, g_gs.e1, 0);
            expand_kernel<<<(N_NODES + EWPB - 1) / EWPB, EWPB * 32, 0, g_gs.s2>>>(
                rf, adj, out_ex);
            cudaEventRecord(g_gs.e2, g_gs.s2);
        } else {
            expand_kernel<<<(N_NODES + EWPB - 1) / EWPB, EWPB * 32>>>(rf, adj, out_ex);
        }
    }

    agg_kernel<<<(N_NODES * 32 + 255) / 256, 256>>>(input, rf);
    dim3 gg((N_NODES + GBM - 1) / GBM, F / GBN);
    gemm_kernel<<<gg, 256, GEMM_SMEM>>>();

    if (fork) cudaStreamWaitEvent(0, g_gs.e2, 0);
    bn_kernel<<<(N_NODES * F / 4 + 255) / 256, 256>>>(gamma, beta, out);
}